// round 1
// baseline (speedup 1.0000x reference)
#include <cuda_runtime.h>
#include <math.h>

#define ROWS 131072
#define HID 256
#define OBS_DIM 128
#define N_ACTIONS 32
#define N_AGENTS 16

// -------- scratch (device globals; no allocations allowed) --------
__device__ float g_x [ROWS * HID];          // encoder output
__device__ float g_h [ROWS * HID];          // hidden state
__device__ float g_c [ROWS * HID];          // comm vector
__device__ float g_gi[ROWS * 3 * HID];      // input gates (biased)
__device__ float g_gh[ROWS * 3 * HID];      // hidden gates (biased)

// -------- generic tiled fp32 GEMM: C[M,N] = act(A[M,K] @ W[N,K]^T + bias) --------
// A row-major [M,K], W row-major [N,K] (so we compute A @ W^T), C row-major [M,N].
// M is always a multiple of 128 here; N may be < BN (decoder) -> guarded.
#define BM 128
#define BN 128
#define BK 16

__global__ __launch_bounds__(256, 2)
void gemm_bias_act(const float* __restrict__ A, const float* __restrict__ W,
                   const float* __restrict__ bias, float* __restrict__ C,
                   int N, int K, int act)
{
    __shared__ float As[BK][BM];
    __shared__ float Ws[BK][BN];

    const int tid  = threadIdx.x;
    const int row0 = blockIdx.y * BM;
    const int col0 = blockIdx.x * BN;

    const int lr = tid >> 1;          // 0..127 : tile row (A) / tile row (W)
    const int lk = (tid & 1) * 8;     // 0 or 8 : k offset within tile
    const int tx = tid & 15;          // 0..15
    const int ty = tid >> 4;          // 0..15

    float acc[8][8];
#pragma unroll
    for (int i = 0; i < 8; i++)
#pragma unroll
        for (int j = 0; j < 8; j++) acc[i][j] = 0.0f;

    const float* Arow = A + (size_t)(row0 + lr) * K + lk;
    const int    wrow = col0 + lr;
    const float* Wrow = W + (size_t)wrow * K + lk;
    const bool   wok  = (wrow < N);

    for (int k0 = 0; k0 < K; k0 += BK) {
        float4 a0 = *(const float4*)(Arow + k0);
        float4 a1 = *(const float4*)(Arow + k0 + 4);
        float4 w0 = make_float4(0.f, 0.f, 0.f, 0.f);
        float4 w1 = make_float4(0.f, 0.f, 0.f, 0.f);
        if (wok) {
            w0 = *(const float4*)(Wrow + k0);
            w1 = *(const float4*)(Wrow + k0 + 4);
        }
        As[lk + 0][lr] = a0.x; As[lk + 1][lr] = a0.y;
        As[lk + 2][lr] = a0.z; As[lk + 3][lr] = a0.w;
        As[lk + 4][lr] = a1.x; As[lk + 5][lr] = a1.y;
        As[lk + 6][lr] = a1.z; As[lk + 7][lr] = a1.w;
        Ws[lk + 0][lr] = w0.x; Ws[lk + 1][lr] = w0.y;
        Ws[lk + 2][lr] = w0.z; Ws[lk + 3][lr] = w0.w;
        Ws[lk + 4][lr] = w1.x; Ws[lk + 5][lr] = w1.y;
        Ws[lk + 6][lr] = w1.z; Ws[lk + 7][lr] = w1.w;
        __syncthreads();

#pragma unroll
        for (int kk = 0; kk < BK; kk++) {
            float ar[8], wr[8];
            *(float4*)&ar[0] = *(const float4*)&As[kk][ty * 8];
            *(float4*)&ar[4] = *(const float4*)&As[kk][ty * 8 + 4];
            *(float4*)&wr[0] = *(const float4*)&Ws[kk][tx * 8];
            *(float4*)&wr[4] = *(const float4*)&Ws[kk][tx * 8 + 4];
#pragma unroll
            for (int i = 0; i < 8; i++)
#pragma unroll
                for (int j = 0; j < 8; j++)
                    acc[i][j] = fmaf(ar[i], wr[j], acc[i][j]);
        }
        __syncthreads();
    }

    // epilogue: bias + optional sigmoid, guarded store
#pragma unroll
    for (int j = 0; j < 8; j++) {
        int c = col0 + tx * 8 + j;
        if (c < N) {
            float b = bias[c];
#pragma unroll
            for (int i = 0; i < 8; i++) {
                float v = acc[i][j] + b;
                if (act == 1) v = 1.0f / (1.0f + expf(-v));
                C[(size_t)(row0 + ty * 8 + i) * N + c] = v;
            }
        }
    }
}

// -------- GRU gate fusion: h_new = (1-z)*n + z*h_prev --------
// gi/gh already include their biases (folded into GEMM epilogue).
__global__ void gate_kernel(const float* __restrict__ gi, const float* __restrict__ gh,
                            const float* __restrict__ hprev, float* __restrict__ hnew)
{
    int idx = blockIdx.x * blockDim.x + threadIdx.x;   // over ROWS*HID
    int row = idx >> 8;
    int j   = idx & 255;
    const float* gir = gi + (size_t)row * (3 * HID);
    const float* ghr = gh + (size_t)row * (3 * HID);
    float ir = gir[j], iz = gir[HID + j], in_ = gir[2 * HID + j];
    float hr = ghr[j], hz = ghr[HID + j], hn  = ghr[2 * HID + j];
    float r = 1.0f / (1.0f + expf(-(ir + hr)));
    float z = 1.0f / (1.0f + expf(-(iz + hz)));
    float n = tanhf(in_ + r * hn);
    float hp = hprev[idx];
    hnew[idx] = (1.0f - z) * n + z * hp;
}

// -------- communication: c[b,a,:] = (sum_a' h[b,a',:] - h[b,a,:]) / N_AGENTS --------
__global__ void comm_kernel(const float* __restrict__ h, float* __restrict__ c)
{
    int b = blockIdx.x;           // 0..8191
    int j = threadIdx.x;          // 0..255
    const float* hb = h + (size_t)b * N_AGENTS * HID;
    float v[N_AGENTS];
    float s = 0.0f;
#pragma unroll
    for (int a = 0; a < N_AGENTS; a++) {
        v[a] = hb[a * HID + j];
        s += v[a];
    }
    float* cb = c + (size_t)b * N_AGENTS * HID;
    const float inv = 1.0f / (float)N_AGENTS;
#pragma unroll
    for (int a = 0; a < N_AGENTS; a++)
        cb[a * HID + j] = (s - v[a]) * inv;
}

extern "C" void kernel_launch(void* const* d_in, const int* in_sizes, int n_in,
                              void* d_out, int out_size)
{
    const float* obs   = (const float*)d_in[0];
    const float* h0    = (const float*)d_in[1];
    const float* enc_w = (const float*)d_in[2];
    const float* enc_b = (const float*)d_in[3];
    const float* w_ih  = (const float*)d_in[4];
    const float* w_hh  = (const float*)d_in[5];
    const float* b_ih  = (const float*)d_in[6];
    const float* b_hh  = (const float*)d_in[7];
    const float* dec_w = (const float*)d_in[8];
    const float* dec_b = (const float*)d_in[9];
    float* out = (float*)d_out;

    float *x, *h, *c, *gi, *gh;
    cudaGetSymbolAddress((void**)&x,  g_x);
    cudaGetSymbolAddress((void**)&h,  g_h);
    cudaGetSymbolAddress((void**)&c,  g_c);
    cudaGetSymbolAddress((void**)&gi, g_gi);
    cudaGetSymbolAddress((void**)&gh, g_gh);

    dim3 t(256);
    dim3 gEnc(HID / BN, ROWS / BM);        // (2, 1024)
    dim3 gG(3 * HID / BN, ROWS / BM);      // (6, 1024)
    dim3 gDec(1, ROWS / BM);               // (1, 1024), N=32 guarded
    const int gateBlocks = (ROWS * HID) / 256;

    // encoder: x = sigmoid(obs @ enc_w^T + enc_b)
    gemm_bias_act<<<gEnc, t>>>(obs, enc_w, enc_b, x, HID, OBS_DIM, 1);

    // GRU cell 1: input x, hidden h0
    gemm_bias_act<<<gG, t>>>(x,  w_ih, b_ih, gi, 3 * HID, HID, 0);
    gemm_bias_act<<<gG, t>>>(h0, w_hh, b_hh, gh, 3 * HID, HID, 0);
    gate_kernel<<<gateBlocks, 256>>>(gi, gh, h0, h);

    // 2 communication steps
    for (int s = 0; s < 2; s++) {
        comm_kernel<<<ROWS / N_AGENTS, 256>>>(h, c);
        gemm_bias_act<<<gG, t>>>(c, w_ih, b_ih, gi, 3 * HID, HID, 0);
        gemm_bias_act<<<gG, t>>>(h, w_hh, b_hh, gh, 3 * HID, HID, 0);
        gate_kernel<<<gateBlocks, 256>>>(gi, gh, h, h);  // in-place safe (elementwise)
    }

    // decoder: weights = h @ dec_w^T + dec_b  -> out[0 : ROWS*N_ACTIONS]
    gemm_bias_act<<<gDec, t>>>(h, dec_w, dec_b, out, N_ACTIONS, HID, 0);

    // h -> out[ROWS*N_ACTIONS : ]
    cudaMemcpyAsync(out + (size_t)ROWS * N_ACTIONS, h,
                    (size_t)ROWS * HID * sizeof(float),
                    cudaMemcpyDeviceToDevice);
}

// round 3
// speedup vs baseline: 3.1673x; 3.1673x over previous
#include <cuda_runtime.h>
#include <math.h>
#include <stdint.h>

#define ROWS 131072
#define HID 256
#define OBS_DIM 128
#define N_ACTIONS 32
#define N_AGENTS 16

// -------- scratch (device globals; no allocations allowed) --------
__device__ float g_x [ROWS * HID];
__device__ float g_h [ROWS * HID];
__device__ float g_c [ROWS * HID];
__device__ float g_gi[ROWS * 3 * HID];
__device__ float g_gh[ROWS * 3 * HID];

// ================= tf32 mma.sync GEMM =================
// C[M, N] = act(A[M, K] @ W[N, K]^T + bias)
// CTA tile 128x128, 8 warps (4 row-groups x 2 col-groups), warp tile 32x64.
// K chunks of 32, cp.async double buffer. Shared rows padded to 36 floats
// (bank index = 4*g + tig  -> conflict-free fragment loads).

#define BM 128
#define BN 128
#define BK 32
#define KPAD 36
#define CHUNK_FLOATS (BM * KPAD)
#define SMEM_FLOATS (4 * CHUNK_FLOATS)          /* A0,A1,B0,B1 */
#define SMEM_SZ (SMEM_FLOATS * 4)

__device__ __forceinline__ uint32_t f2tf32(float x) {
    uint32_t r;
    asm("cvt.rna.tf32.f32 %0, %1;" : "=r"(r) : "f"(x));
    return r;
}

__device__ __forceinline__ void mma_tf32(float* d, const uint32_t* a, const uint32_t* b) {
    asm volatile(
        "mma.sync.aligned.m16n8k8.row.col.f32.tf32.tf32.f32 "
        "{%0,%1,%2,%3}, {%4,%5,%6,%7}, {%8,%9}, {%0,%1,%2,%3};"
        : "+f"(d[0]), "+f"(d[1]), "+f"(d[2]), "+f"(d[3])
        : "r"(a[0]), "r"(a[1]), "r"(a[2]), "r"(a[3]), "r"(b[0]), "r"(b[1]));
}

__global__ __launch_bounds__(256)
void mma_gemm(const float* __restrict__ A, const float* __restrict__ W,
              const float* __restrict__ bias, float* __restrict__ C,
              int K, int N, int act)
{
    extern __shared__ float sm[];
    float* As = sm;                       // [2][BM][KPAD]
    float* Bs = sm + 2 * CHUNK_FLOATS;    // [2][BN][KPAD]

    const int tid = threadIdx.x;
    const int wid = tid >> 5, lid = tid & 31;
    const int wm = wid & 3, wn = wid >> 2;       // warp grid 4 x 2
    const int g = lid >> 2, tig = lid & 3;
    const int row0 = blockIdx.y * BM;
    const int col0 = blockIdx.x * BN;
    const int NC = K / BK;

    // cp.async load indices: 1024 float4 per chunk / 256 threads = 4 each
    const int lr = tid >> 1;                     // pair-rows: see below
    (void)lr;

    float d[2][8][4];
#pragma unroll
    for (int mt = 0; mt < 2; mt++)
#pragma unroll
        for (int nt = 0; nt < 8; nt++)
#pragma unroll
            for (int e = 0; e < 4; e++) d[mt][nt][e] = 0.0f;

#define PREFETCH(kc) do {                                                        \
        int buf_ = (kc) & 1;                                                     \
        float* Ad_ = As + buf_ * CHUNK_FLOATS;                                   \
        float* Bd_ = Bs + buf_ * CHUNK_FLOATS;                                   \
        _Pragma("unroll")                                                        \
        for (int i_ = 0; i_ < 4; i_++) {                                         \
            int idx_ = tid + i_ * 256;                                           \
            int r_ = idx_ >> 3, q_ = idx_ & 7;                                   \
            uint32_t adst_ = (uint32_t)__cvta_generic_to_shared(                 \
                                 Ad_ + r_ * KPAD + q_ * 4);                      \
            const float* asrc_ = A + (size_t)(row0 + r_) * K + (kc) * BK + q_*4; \
            asm volatile("cp.async.cg.shared.global [%0], [%1], 16;"             \
                         :: "r"(adst_), "l"(asrc_));                             \
            uint32_t bdst_ = (uint32_t)__cvta_generic_to_shared(                 \
                                 Bd_ + r_ * KPAD + q_ * 4);                      \
            const float* bsrc_ = W + (size_t)(col0 + r_) * K + (kc) * BK + q_*4; \
            if (col0 + r_ < N)                                                   \
                asm volatile("cp.async.cg.shared.global [%0], [%1], 16;"         \
                             :: "r"(bdst_), "l"(bsrc_));                         \
            else                                                                 \
                asm volatile("cp.async.cg.shared.global [%0], [%1], 16, 0;"      \
                             :: "r"(bdst_), "l"(W));                             \
        }                                                                        \
        asm volatile("cp.async.commit_group;");                                  \
    } while (0)

    PREFETCH(0);

    for (int kc = 0; kc < NC; kc++) {
        if (kc + 1 < NC) {
            PREFETCH(kc + 1);
            asm volatile("cp.async.wait_group 1;");
        } else {
            asm volatile("cp.async.wait_group 0;");
        }
        __syncthreads();

        const float* Ab = As + (kc & 1) * CHUNK_FLOATS;
        const float* Bb = Bs + (kc & 1) * CHUNK_FLOATS;

#pragma unroll
        for (int ks = 0; ks < 4; ks++) {
            uint32_t a[2][4], b[8][2];
#pragma unroll
            for (int mt = 0; mt < 2; mt++) {
                const float* ap = Ab + (wm * 32 + mt * 16 + g) * KPAD + ks * 8 + tig;
                a[mt][0] = f2tf32(ap[0]);
                a[mt][1] = f2tf32(ap[8 * KPAD]);
                a[mt][2] = f2tf32(ap[4]);
                a[mt][3] = f2tf32(ap[8 * KPAD + 4]);
            }
#pragma unroll
            for (int nt = 0; nt < 8; nt++) {
                const float* bp = Bb + (wn * 64 + nt * 8 + g) * KPAD + ks * 8 + tig;
                b[nt][0] = f2tf32(bp[0]);
                b[nt][1] = f2tf32(bp[4]);
            }
#pragma unroll
            for (int mt = 0; mt < 2; mt++)
#pragma unroll
                for (int nt = 0; nt < 8; nt++)
                    mma_tf32(d[mt][nt], a[mt], b[nt]);
        }
        __syncthreads();
    }
#undef PREFETCH

    // -------- epilogue: bias + optional sigmoid, float2 stores --------
#pragma unroll
    for (int nt = 0; nt < 8; nt++) {
        int col = col0 + wn * 64 + nt * 8 + 2 * tig;
        if (col < N) {
            float b0 = bias[col], b1 = bias[col + 1];
#pragma unroll
            for (int mt = 0; mt < 2; mt++) {
                int row = row0 + wm * 32 + mt * 16 + g;
                float2 v0, v1;
                v0.x = d[mt][nt][0] + b0;  v0.y = d[mt][nt][1] + b1;
                v1.x = d[mt][nt][2] + b0;  v1.y = d[mt][nt][3] + b1;
                if (act) {
                    v0.x = 1.0f / (1.0f + __expf(-v0.x));
                    v0.y = 1.0f / (1.0f + __expf(-v0.y));
                    v1.x = 1.0f / (1.0f + __expf(-v1.x));
                    v1.y = 1.0f / (1.0f + __expf(-v1.y));
                }
                *(float2*)(C + (size_t)row * N + col) = v0;
                *(float2*)(C + (size_t)(row + 8) * N + col) = v1;
            }
        }
    }
}

// -------- GRU gate fusion (float4): h_new = (1-z)*n + z*h_prev --------
__device__ __forceinline__ float gatef(float ir, float iz, float in_,
                                       float hr, float hz, float hn, float hp) {
    float r = 1.0f / (1.0f + __expf(-(ir + hr)));
    float z = 1.0f / (1.0f + __expf(-(iz + hz)));
    float n = tanhf(in_ + r * hn);
    return (1.0f - z) * n + z * hp;
}

__global__ void gate_kernel(const float* __restrict__ gi, const float* __restrict__ gh,
                            const float* __restrict__ hprev, float* __restrict__ hnew,
                            float* __restrict__ hout2)
{
    int idx = blockIdx.x * blockDim.x + threadIdx.x;    // over ROWS*64 float4s
    int row = idx >> 6, j = idx & 63;
    const float4* gir = (const float4*)(gi + (size_t)row * 768) + j;
    const float4* ghr = (const float4*)(gh + (size_t)row * 768) + j;
    float4 ir = gir[0], iz = gir[64], in4 = gir[128];
    float4 hr = ghr[0], hz = ghr[64], hn4 = ghr[128];
    float4 hp = ((const float4*)hprev)[idx];
    float4 o;
    o.x = gatef(ir.x, iz.x, in4.x, hr.x, hz.x, hn4.x, hp.x);
    o.y = gatef(ir.y, iz.y, in4.y, hr.y, hz.y, hn4.y, hp.y);
    o.z = gatef(ir.z, iz.z, in4.z, hr.z, hz.z, hn4.z, hp.z);
    o.w = gatef(ir.w, iz.w, in4.w, hr.w, hz.w, hn4.w, hp.w);
    ((float4*)hnew)[idx] = o;
    if (hout2) ((float4*)hout2)[idx] = o;
}

// -------- communication: c[b,a,:] = (sum_a' h[b,a',:] - h[b,a,:]) / N_AGENTS --------
__global__ void comm_kernel(const float4* __restrict__ h, float4* __restrict__ c)
{
    int t = blockIdx.x * blockDim.x + threadIdx.x;      // (ROWS/16)*64
    int b = t >> 6, j = t & 63;
    const float4* hb = h + (size_t)b * (N_AGENTS * 64) + j;
    float4 v[N_AGENTS];
    float4 s = make_float4(0.f, 0.f, 0.f, 0.f);
#pragma unroll
    for (int a = 0; a < N_AGENTS; a++) {
        v[a] = hb[a * 64];
        s.x += v[a].x; s.y += v[a].y; s.z += v[a].z; s.w += v[a].w;
    }
    float4* cb = c + (size_t)b * (N_AGENTS * 64) + j;
    const float inv = 1.0f / (float)N_AGENTS;
#pragma unroll
    for (int a = 0; a < N_AGENTS; a++) {
        float4 o;
        o.x = (s.x - v[a].x) * inv;
        o.y = (s.y - v[a].y) * inv;
        o.z = (s.z - v[a].z) * inv;
        o.w = (s.w - v[a].w) * inv;
        cb[a * 64] = o;
    }
}

extern "C" void kernel_launch(void* const* d_in, const int* in_sizes, int n_in,
                              void* d_out, int out_size)
{
    const float* obs   = (const float*)d_in[0];
    const float* h0    = (const float*)d_in[1];
    const float* enc_w = (const float*)d_in[2];
    const float* enc_b = (const float*)d_in[3];
    const float* w_ih  = (const float*)d_in[4];
    const float* w_hh  = (const float*)d_in[5];
    const float* b_ih  = (const float*)d_in[6];
    const float* b_hh  = (const float*)d_in[7];
    const float* dec_w = (const float*)d_in[8];
    const float* dec_b = (const float*)d_in[9];
    float* out = (float*)d_out;

    float *x, *h, *c, *gi, *gh;
    cudaGetSymbolAddress((void**)&x,  g_x);
    cudaGetSymbolAddress((void**)&h,  g_h);
    cudaGetSymbolAddress((void**)&c,  g_c);
    cudaGetSymbolAddress((void**)&gi, g_gi);
    cudaGetSymbolAddress((void**)&gh, g_gh);

    cudaFuncSetAttribute(mma_gemm, cudaFuncAttributeMaxDynamicSharedMemorySize, SMEM_SZ);

    dim3 t(256);
    dim3 gEnc(HID / BN, ROWS / BM);          // (2, 1024)
    dim3 gG(3 * HID / BN, ROWS / BM);        // (6, 1024)
    dim3 gDec(1, ROWS / BM);                 // (1, 1024), N=32 guarded
    const int gateBlocks = (ROWS * HID / 4) / 256;                 // 32768
    const int commBlocks = ((ROWS / N_AGENTS) * (HID / 4)) / 256;  // 2048

    // encoder: x = sigmoid(obs @ enc_w^T + enc_b)
    mma_gemm<<<gEnc, t, SMEM_SZ>>>(obs, enc_w, enc_b, x, OBS_DIM, HID, 1);

    // GRU cell 1
    mma_gemm<<<gG, t, SMEM_SZ>>>(x,  w_ih, b_ih, gi, HID, 3 * HID, 0);
    mma_gemm<<<gG, t, SMEM_SZ>>>(h0, w_hh, b_hh, gh, HID, 3 * HID, 0);
    gate_kernel<<<gateBlocks, 256>>>(gi, gh, h0, h, nullptr);

    // 2 communication steps; last gate also writes h into d_out tail
    for (int s = 0; s < 2; s++) {
        comm_kernel<<<commBlocks, 256>>>((const float4*)h, (float4*)c);
        mma_gemm<<<gG, t, SMEM_SZ>>>(c, w_ih, b_ih, gi, HID, 3 * HID, 0);
        mma_gemm<<<gG, t, SMEM_SZ>>>(h, w_hh, b_hh, gh, HID, 3 * HID, 0);
        float* h2 = (s == 1) ? (out + (size_t)ROWS * N_ACTIONS) : nullptr;
        gate_kernel<<<gateBlocks, 256>>>(gi, gh, h, h, h2);
    }

    // decoder: weights = h @ dec_w^T + dec_b
    mma_gemm<<<gDec, t, SMEM_SZ>>>(h, dec_w, dec_b, out, HID, N_ACTIONS, 0);
}

// round 4
// speedup vs baseline: 5.8086x; 1.8339x over previous
#include <cuda_runtime.h>
#include <cuda_fp16.h>
#include <math.h>
#include <stdint.h>

#define ROWS 131072
#define HID 256
#define OBS_DIM 128
#define N_ACTIONS 32
#define N_AGENTS 16

// -------- scratch (device globals; no allocations allowed) --------
__device__ __half g_x16 [ROWS * HID];        // encoder out / comm out (GEMM A input)
__device__ __half g_h16a[ROWS * HID];
__device__ __half g_h16b[ROWS * HID];
__device__ float  g_h32a[ROWS * HID];
__device__ float  g_h32b[ROWS * HID];
__device__ __half g_obs16[ROWS * OBS_DIM];
__device__ __half g_h016[ROWS * HID];
__device__ __half g_wf  [1024 * 512];        // fused gate-interleaved GRU weights
__device__ float  g_gb  [1024];              // [gate][j] biases: r-comb, z-comb, i_n, h_n
__device__ __half g_encw[HID * OBS_DIM];
__device__ __half g_decw[N_ACTIONS * HID];

// ================= shared GEMM geometry =================
// CTA tile 128x128, 8 warps (4 row x 2 col), warp tile 32x64.
// K chunks of 64 halves (128 B rows), padded to 72 halves (144 B) -> the
// fragment LDS.32 pattern (bank = 4*g + tig per row-octet) is conflict-free.
#define FBK 64
#define FPITCH 72
#define FCHUNK (128 * FPITCH)            /* halves per (tile, buffer) */
#define FSMEM_BYTES (4 * FCHUNK * 2)     /* A0,A1,B0,B1 = 73728 B */

__device__ __forceinline__ void mma_f16(float* d, const uint32_t* a, const uint32_t* b) {
    asm volatile(
        "mma.sync.aligned.m16n8k16.row.col.f32.f16.f16.f32 "
        "{%0,%1,%2,%3}, {%4,%5,%6,%7}, {%8,%9}, {%0,%1,%2,%3};"
        : "+f"(d[0]), "+f"(d[1]), "+f"(d[2]), "+f"(d[3])
        : "r"(a[0]), "r"(a[1]), "r"(a[2]), "r"(a[3]), "r"(b[0]), "r"(b[1]));
}

__device__ __forceinline__ float sigf(float u) { return 1.0f / (1.0f + __expf(-u)); }
__device__ __forceinline__ float tanhfast(float t) {
    float e = __expf(-2.0f * fabsf(t));
    return copysignf((1.0f - e) / (1.0f + e), t);
}

// cp.async helpers
__device__ __forceinline__ void cpa16(uint32_t dst, const void* src) {
    asm volatile("cp.async.cg.shared.global [%0], [%1], 16;" :: "r"(dst), "l"(src));
}
__device__ __forceinline__ void cpa16z(uint32_t dst, const void* src, bool ok) {
    if (ok) asm volatile("cp.async.cg.shared.global [%0], [%1], 16;" :: "r"(dst), "l"(src));
    else    asm volatile("cp.async.cg.shared.global [%0], [%1], 16, 0;" :: "r"(dst), "l"(src));
}

// ================= fused GRU cell kernel =================
// Computes, for its 128-row x 32-hidden tile (N_eff = 1024 interleaved cols):
//   rsum = [x|h] @ Wr_cat^T ; zsum = [x|h] @ Wz_cat^T ; i_n = x @ Wn_ih^T ; h_n = h @ Wn_hh^T
//   h_new = (1-z)*n + z*h_prev   (biases folded from g_gb)
// Column interleave c = 32*(j>>3) + 8*g + (j&7): each n8 MMA tile is single-gate,
// so x-phase skips g==3 tiles and h-phase skips g==2 tiles (no wasted FLOPs),
// and one thread's fragments hold all 4 gates of hidden units (J, J+1).
__global__ __launch_bounds__(256, 2)
void fused_gru(const __half* __restrict__ Ax, const __half* __restrict__ Ah,
               const float* __restrict__ hprev, float* __restrict__ h32out,
               __half* __restrict__ h16out)
{
    extern __shared__ __half sm[];
    __half* As = sm;
    __half* Bs = sm + 2 * FCHUNK;
    const __half* Wf = g_wf;

    const int tid = threadIdx.x;
    const int wid = tid >> 5, lid = tid & 31;
    const int wm = wid & 3, wn = wid >> 2;
    const int gq = lid >> 2, tig = lid & 3;
    const int row0 = blockIdx.y * 128;
    const int col0 = blockIdx.x * 128;

    float d[2][8][4];
#pragma unroll
    for (int mt = 0; mt < 2; mt++)
#pragma unroll
        for (int nt = 0; nt < 8; nt++)
#pragma unroll
            for (int e = 0; e < 4; e++) d[mt][nt][e] = 0.0f;

#define FPREF(kc) do {                                                          \
        int buf_ = (kc) & 1;                                                    \
        const __half* as_ = ((kc) < 4) ? Ax + (size_t)row0 * HID + (kc) * FBK   \
                                       : Ah + (size_t)row0 * HID + ((kc)-4)*FBK;\
        _Pragma("unroll")                                                       \
        for (int i_ = 0; i_ < 4; i_++) {                                        \
            int idx_ = tid + i_ * 256;                                          \
            int r_ = idx_ >> 3, q_ = idx_ & 7;                                  \
            uint32_t ad_ = (uint32_t)__cvta_generic_to_shared(                  \
                               As + buf_ * FCHUNK + r_ * FPITCH + q_ * 8);      \
            cpa16(ad_, as_ + (size_t)r_ * HID + q_ * 8);                        \
            uint32_t bd_ = (uint32_t)__cvta_generic_to_shared(                  \
                               Bs + buf_ * FCHUNK + r_ * FPITCH + q_ * 8);      \
            cpa16(bd_, Wf + (size_t)(col0 + r_) * 512 + (kc) * FBK + q_ * 8);   \
        }                                                                       \
        asm volatile("cp.async.commit_group;");                                 \
    } while (0)

    FPREF(0);

    for (int kc = 0; kc < 8; kc++) {
        if (kc + 1 < 8) {
            FPREF(kc + 1);
            asm volatile("cp.async.wait_group 1;");
        } else {
            asm volatile("cp.async.wait_group 0;");
        }
        __syncthreads();

        const __half* Ab = As + (kc & 1) * FCHUNK;
        const __half* Bb = Bs + (kc & 1) * FCHUNK;
        const int skipg = (kc < 4) ? 3 : 2;

#pragma unroll
        for (int ks = 0; ks < 4; ks++) {
            uint32_t a[2][4];
#pragma unroll
            for (int mt = 0; mt < 2; mt++) {
                const __half* ap = Ab + (wm * 32 + mt * 16 + gq) * FPITCH + ks * 16;
                a[mt][0] = *(const uint32_t*)(ap + 2 * tig);
                a[mt][1] = *(const uint32_t*)(ap + 8 * FPITCH + 2 * tig);
                a[mt][2] = *(const uint32_t*)(ap + 2 * tig + 8);
                a[mt][3] = *(const uint32_t*)(ap + 8 * FPITCH + 2 * tig + 8);
            }
#pragma unroll
            for (int nt = 0; nt < 8; nt++) {
                if ((nt & 3) == skipg) continue;
                const __half* bp = Bb + (wn * 64 + nt * 8 + gq) * FPITCH + ks * 16 + 2 * tig;
                uint32_t b[2];
                b[0] = *(const uint32_t*)bp;
                b[1] = *(const uint32_t*)(bp + 8);
                mma_f16(d[0][nt], a[0], b);
                mma_f16(d[1][nt], a[1], b);
            }
        }
        __syncthreads();
    }
#undef FPREF

    // -------- epilogue: gate math + h store --------
    const float* gb = g_gb;
#pragma unroll
    for (int a2 = 0; a2 < 2; a2++) {
        const int J = (col0 >> 2) + wn * 16 + a2 * 8 + 2 * tig;   // col0/4 = bx*32
        const float bR0 = gb[J],       bR1 = gb[J + 1];
        const float bZ0 = gb[256 + J], bZ1 = gb[256 + J + 1];
        const float bI0 = gb[512 + J], bI1 = gb[512 + J + 1];
        const float bH0 = gb[768 + J], bH1 = gb[768 + J + 1];
#pragma unroll
        for (int mt = 0; mt < 2; mt++) {
            const int rowa = row0 + wm * 32 + mt * 16 + gq;
#pragma unroll
            for (int half = 0; half < 2; half++) {
                const int row = rowa + half * 8;
                const int e0 = half * 2, e1 = half * 2 + 1;
                float r0 = sigf(d[mt][4 * a2 + 0][e0] + bR0);
                float r1 = sigf(d[mt][4 * a2 + 0][e1] + bR1);
                float z0 = sigf(d[mt][4 * a2 + 1][e0] + bZ0);
                float z1 = sigf(d[mt][4 * a2 + 1][e1] + bZ1);
                float n0 = tanhfast(d[mt][4 * a2 + 2][e0] + bI0 + r0 * (d[mt][4 * a2 + 3][e0] + bH0));
                float n1 = tanhfast(d[mt][4 * a2 + 2][e1] + bI1 + r1 * (d[mt][4 * a2 + 3][e1] + bH1));
                float2 hp = *(const float2*)(hprev + (size_t)row * HID + J);
                float h0 = (1.0f - z0) * n0 + z0 * hp.x;
                float h1 = (1.0f - z1) * n1 + z1 * hp.y;
                *(float2*)(h32out + (size_t)row * HID + J) = make_float2(h0, h1);
                *(__half2*)(h16out + (size_t)row * HID + J) = __floats2half2_rn(h0, h1);
            }
        }
    }
}

// ================= generic fp16 GEMM (encoder / decoder) =================
// C[M,N] = act(A[M,K]@W[N,K]^T + bias); optional fp32 and/or fp16 outputs.
__global__ __launch_bounds__(256, 2)
void hgemm(const __half* __restrict__ A, const __half* __restrict__ W,
           const float* __restrict__ bias, float* __restrict__ C32,
           __half* __restrict__ C16, int K, int N, int act)
{
    extern __shared__ __half sm[];
    __half* As = sm;
    __half* Bs = sm + 2 * FCHUNK;

    const int tid = threadIdx.x;
    const int wid = tid >> 5, lid = tid & 31;
    const int wm = wid & 3, wn = wid >> 2;
    const int gq = lid >> 2, tig = lid & 3;
    const int row0 = blockIdx.y * 128;
    const int col0 = blockIdx.x * 128;
    const int NC = K / FBK;

    float d[2][8][4];
#pragma unroll
    for (int mt = 0; mt < 2; mt++)
#pragma unroll
        for (int nt = 0; nt < 8; nt++)
#pragma unroll
            for (int e = 0; e < 4; e++) d[mt][nt][e] = 0.0f;

#define GPREF(kc) do {                                                          \
        int buf_ = (kc) & 1;                                                    \
        _Pragma("unroll")                                                       \
        for (int i_ = 0; i_ < 4; i_++) {                                        \
            int idx_ = tid + i_ * 256;                                          \
            int r_ = idx_ >> 3, q_ = idx_ & 7;                                  \
            uint32_t ad_ = (uint32_t)__cvta_generic_to_shared(                  \
                               As + buf_ * FCHUNK + r_ * FPITCH + q_ * 8);      \
            cpa16(ad_, A + (size_t)(row0 + r_) * K + (kc) * FBK + q_ * 8);      \
            uint32_t bd_ = (uint32_t)__cvta_generic_to_shared(                  \
                               Bs + buf_ * FCHUNK + r_ * FPITCH + q_ * 8);      \
            cpa16z(bd_, W + (size_t)(col0 + r_) * K + (kc) * FBK + q_ * 8,      \
                   col0 + r_ < N);                                              \
        }                                                                       \
        asm volatile("cp.async.commit_group;");                                 \
    } while (0)

    GPREF(0);

    for (int kc = 0; kc < NC; kc++) {
        if (kc + 1 < NC) {
            GPREF(kc + 1);
            asm volatile("cp.async.wait_group 1;");
        } else {
            asm volatile("cp.async.wait_group 0;");
        }
        __syncthreads();

        const __half* Ab = As + (kc & 1) * FCHUNK;
        const __half* Bb = Bs + (kc & 1) * FCHUNK;
#pragma unroll
        for (int ks = 0; ks < 4; ks++) {
            uint32_t a[2][4];
#pragma unroll
            for (int mt = 0; mt < 2; mt++) {
                const __half* ap = Ab + (wm * 32 + mt * 16 + gq) * FPITCH + ks * 16;
                a[mt][0] = *(const uint32_t*)(ap + 2 * tig);
                a[mt][1] = *(const uint32_t*)(ap + 8 * FPITCH + 2 * tig);
                a[mt][2] = *(const uint32_t*)(ap + 2 * tig + 8);
                a[mt][3] = *(const uint32_t*)(ap + 8 * FPITCH + 2 * tig + 8);
            }
#pragma unroll
            for (int nt = 0; nt < 8; nt++) {
                const __half* bp = Bb + (wn * 64 + nt * 8 + gq) * FPITCH + ks * 16 + 2 * tig;
                uint32_t b[2];
                b[0] = *(const uint32_t*)bp;
                b[1] = *(const uint32_t*)(bp + 8);
                mma_f16(d[0][nt], a[0], b);
                mma_f16(d[1][nt], a[1], b);
            }
        }
        __syncthreads();
    }
#undef GPREF

#pragma unroll
    for (int nt = 0; nt < 8; nt++) {
        int col = col0 + wn * 64 + nt * 8 + 2 * tig;
        if (col < N) {
            float b0 = bias[col], b1 = bias[col + 1];
#pragma unroll
            for (int mt = 0; mt < 2; mt++) {
                int rowa = row0 + wm * 32 + mt * 16 + gq;
#pragma unroll
                for (int half = 0; half < 2; half++) {
                    int row = rowa + half * 8;
                    float v0 = d[mt][nt][half * 2]     + b0;
                    float v1 = d[mt][nt][half * 2 + 1] + b1;
                    if (act) { v0 = sigf(v0); v1 = sigf(v1); }
                    if (C32) *(float2*)(C32 + (size_t)row * N + col) = make_float2(v0, v1);
                    if (C16) *(__half2*)(C16 + (size_t)row * N + col) = __floats2half2_rn(v0, v1);
                }
            }
        }
    }
}

// ================= prep + elementwise kernels =================
__global__ void f2h_kernel(const float4* __restrict__ src, __half2* __restrict__ dst, int n4)
{
    int i = blockIdx.x * blockDim.x + threadIdx.x;
    if (i < n4) {
        float4 v = src[i];
        dst[2 * i]     = __floats2half2_rn(v.x, v.y);
        dst[2 * i + 1] = __floats2half2_rn(v.z, v.w);
    }
}

__global__ void build_wf_kernel(const float* __restrict__ w_ih, const float* __restrict__ w_hh)
{
    int idx = blockIdx.x * blockDim.x + threadIdx.x;   // 1024*512
    if (idx >= 1024 * 512) return;
    int c = idx >> 9, k = idx & 511;
    int g = (c >> 3) & 3;
    int j = ((c >> 5) << 3) + (c & 7);
    float v;
    if (g == 0)      v = (k < 256) ? w_ih[j * 256 + k]           : w_hh[j * 256 + k - 256];
    else if (g == 1) v = (k < 256) ? w_ih[(256 + j) * 256 + k]   : w_hh[(256 + j) * 256 + k - 256];
    else if (g == 2) v = (k < 256) ? w_ih[(512 + j) * 256 + k]   : 0.0f;
    else             v = (k < 256) ? 0.0f                        : w_hh[(512 + j) * 256 + k - 256];
    g_wf[c * 512 + k] = __float2half_rn(v);
}

__global__ void build_gb_kernel(const float* __restrict__ b_ih, const float* __restrict__ b_hh)
{
    int idx = threadIdx.x + blockIdx.x * blockDim.x;   // 1024
    if (idx >= 1024) return;
    int g = idx >> 8, j = idx & 255;
    float v;
    if (g == 0)      v = b_ih[j] + b_hh[j];
    else if (g == 1) v = b_ih[256 + j] + b_hh[256 + j];
    else if (g == 2) v = b_ih[512 + j];
    else             v = b_hh[512 + j];
    g_gb[idx] = v;
}

// comm: c[b,a,:] = (sum_a' h[b,a',:] - h[b,a,:]) / N_AGENTS   (fp16 in/out, fp32 math)
__global__ void comm16_kernel(const __half2* __restrict__ h, __half2* __restrict__ c)
{
    int t = blockIdx.x * blockDim.x + threadIdx.x;     // (ROWS/16)*(HID/2)
    int b = t >> 7, j = t & 127;
    const __half2* hb = h + (size_t)b * (N_AGENTS * 128) + j;
    float2 v[N_AGENTS];
    float sx = 0.f, sy = 0.f;
#pragma unroll
    for (int a = 0; a < N_AGENTS; a++) {
        v[a] = __half22float2(hb[a * 128]);
        sx += v[a].x; sy += v[a].y;
    }
    __half2* cb = c + (size_t)b * (N_AGENTS * 128) + j;
    const float inv = 1.0f / (float)N_AGENTS;
#pragma unroll
    for (int a = 0; a < N_AGENTS; a++)
        cb[a * 128] = __floats2half2_rn((sx - v[a].x) * inv, (sy - v[a].y) * inv);
}

extern "C" void kernel_launch(void* const* d_in, const int* in_sizes, int n_in,
                              void* d_out, int out_size)
{
    const float* obs   = (const float*)d_in[0];
    const float* h0    = (const float*)d_in[1];
    const float* enc_w = (const float*)d_in[2];
    const float* enc_b = (const float*)d_in[3];
    const float* w_ih  = (const float*)d_in[4];
    const float* w_hh  = (const float*)d_in[5];
    const float* b_ih  = (const float*)d_in[6];
    const float* b_hh  = (const float*)d_in[7];
    const float* dec_w = (const float*)d_in[8];
    const float* dec_b = (const float*)d_in[9];
    float* out = (float*)d_out;

    __half *x16, *h16a, *h16b, *obs16, *h016, *encw, *decw;
    float *h32a, *h32b;
    cudaGetSymbolAddress((void**)&x16,   g_x16);
    cudaGetSymbolAddress((void**)&h16a,  g_h16a);
    cudaGetSymbolAddress((void**)&h16b,  g_h16b);
    cudaGetSymbolAddress((void**)&h32a,  g_h32a);
    cudaGetSymbolAddress((void**)&h32b,  g_h32b);
    cudaGetSymbolAddress((void**)&obs16, g_obs16);
    cudaGetSymbolAddress((void**)&h016,  g_h016);
    cudaGetSymbolAddress((void**)&encw,  g_encw);
    cudaGetSymbolAddress((void**)&decw,  g_decw);

    cudaFuncSetAttribute(fused_gru, cudaFuncAttributeMaxDynamicSharedMemorySize, FSMEM_BYTES);
    cudaFuncSetAttribute(hgemm,     cudaFuncAttributeMaxDynamicSharedMemorySize, FSMEM_BYTES);

    // ---- prep (fp32 -> fp16 / fused weight layout) ----
    f2h_kernel<<<(ROWS * OBS_DIM / 4 + 255) / 256, 256>>>((const float4*)obs, (__half2*)obs16, ROWS * OBS_DIM / 4);
    f2h_kernel<<<(ROWS * HID / 4 + 255) / 256, 256>>>((const float4*)h0, (__half2*)h016, ROWS * HID / 4);
    f2h_kernel<<<(HID * OBS_DIM / 4 + 255) / 256, 256>>>((const float4*)enc_w, (__half2*)encw, HID * OBS_DIM / 4);
    f2h_kernel<<<(N_ACTIONS * HID / 4 + 255) / 256, 256>>>((const float4*)dec_w, (__half2*)decw, N_ACTIONS * HID / 4);
    build_wf_kernel<<<(1024 * 512) / 256, 256>>>(w_ih, w_hh);
    build_gb_kernel<<<4, 256>>>(b_ih, b_hh);

    dim3 t(256);
    const int commBlocks = ((ROWS / N_AGENTS) * (HID / 2)) / 256;   // 4096

    // encoder: x16 = sigmoid(obs @ enc_w^T + enc_b)
    hgemm<<<dim3(2, ROWS / 128), t, FSMEM_BYTES>>>(obs16, encw, enc_b, nullptr, x16, OBS_DIM, HID, 1);

    // GRU cell 1: inputs x16 / h016, hprev = h0 (fp32)
    fused_gru<<<dim3(8, ROWS / 128), t, FSMEM_BYTES>>>(x16, h016, h0, h32a, h16a);

    // comm 1 + cell 2
    comm16_kernel<<<commBlocks, 256>>>((const __half2*)h16a, (__half2*)x16);
    fused_gru<<<dim3(8, ROWS / 128), t, FSMEM_BYTES>>>(x16, h16a, h32a, h32b, h16b);

    // comm 2 + cell 3 (h32 goes straight into d_out tail)
    comm16_kernel<<<commBlocks, 256>>>((const __half2*)h16b, (__half2*)x16);
    fused_gru<<<dim3(8, ROWS / 128), t, FSMEM_BYTES>>>(x16, h16b, h32b,
                                                      out + (size_t)ROWS * N_ACTIONS, h16a);

    // decoder: weights = h @ dec_w^T + dec_b
    hgemm<<<dim3(1, ROWS / 128), t, FSMEM_BYTES>>>(h16a, decw, dec_b, out, nullptr, HID, N_ACTIONS, 0);
}

// round 5
// speedup vs baseline: 6.6869x; 1.1512x over previous
#include <cuda_runtime.h>
#include <cuda_fp16.h>
#include <math.h>
#include <stdint.h>

#define ROWS 131072
#define HID 256
#define OBS_DIM 128
#define N_ACTIONS 32
#define N_AGENTS 16
#define NGROUP (ROWS / N_AGENTS)     /* 8192 */

// -------- scratch (device globals; no allocations allowed) --------
__device__ __half g_x16 [ROWS * HID];
__device__ __half g_h16a[ROWS * HID];
__device__ __half g_h16b[ROWS * HID];
__device__ float  g_h32a[ROWS * HID];
__device__ float  g_h32b[ROWS * HID];
__device__ __half g_obs16[ROWS * OBS_DIM];
__device__ __half g_h016[ROWS * HID];
__device__ __half g_wf  [1024 * 512];      // cell-1 fused weights (interleaved, K=512)
__device__ __half g_wf2 [1024 * 256];      // cells-2/3 combined weights (interleaved, K=256)
__device__ __half g_ws16[768 * 256];       // W_ih / 16 (planar) for the S GEMM
__device__ float  g_gb  [1024];            // biases: r-comb, z-comb, i_n, h_n
__device__ __half g_S16 [NGROUP * HID];    // per-group agent sums
__device__ float  g_Sg  [NGROUP * 768];    // S @ Ws^T (planar: gate*256 + j)
__device__ __half g_encw[HID * OBS_DIM];
__device__ __half g_decw[N_ACTIONS * HID];

// ================= shared GEMM geometry =================
#define FBK 64
#define FPITCH 72
#define FCHUNK (128 * FPITCH)
#define FSMEM_BYTES (4 * FCHUNK * 2)

__device__ __forceinline__ void mma_f16(float* d, const uint32_t* a, const uint32_t* b) {
    asm volatile(
        "mma.sync.aligned.m16n8k16.row.col.f32.f16.f16.f32 "
        "{%0,%1,%2,%3}, {%4,%5,%6,%7}, {%8,%9}, {%0,%1,%2,%3};"
        : "+f"(d[0]), "+f"(d[1]), "+f"(d[2]), "+f"(d[3])
        : "r"(a[0]), "r"(a[1]), "r"(a[2]), "r"(a[3]), "r"(b[0]), "r"(b[1]));
}

__device__ __forceinline__ float sigf(float u) { return 1.0f / (1.0f + __expf(-u)); }
__device__ __forceinline__ float tanhfast(float t) {
    float e = __expf(-2.0f * fabsf(t));
    return copysignf((1.0f - e) / (1.0f + e), t);
}

__device__ __forceinline__ void cpa16(uint32_t dst, const void* src) {
    asm volatile("cp.async.cg.shared.global [%0], [%1], 16;" :: "r"(dst), "l"(src));
}
__device__ __forceinline__ void cpa16z(uint32_t dst, const void* src, bool ok) {
    if (ok) asm volatile("cp.async.cg.shared.global [%0], [%1], 16;" :: "r"(dst), "l"(src));
    else    asm volatile("cp.async.cg.shared.global [%0], [%1], 16, 0;" :: "r"(dst), "l"(src));
}

// ================= cell-1 fused GRU (A = [x | h], K=512, gate-skipped) =================
__global__ __launch_bounds__(256, 2)
void fused_gru(const __half* __restrict__ Ax, const __half* __restrict__ Ah,
               const float* __restrict__ hprev, float* __restrict__ h32out,
               __half* __restrict__ h16out)
{
    extern __shared__ __half sm[];
    __half* As = sm;
    __half* Bs = sm + 2 * FCHUNK;
    const __half* Wf = g_wf;

    const int tid = threadIdx.x;
    const int wid = tid >> 5, lid = tid & 31;
    const int wm = wid & 3, wn = wid >> 2;
    const int gq = lid >> 2, tig = lid & 3;
    const int row0 = blockIdx.y * 128;
    const int col0 = blockIdx.x * 128;

    float d[2][8][4];
#pragma unroll
    for (int mt = 0; mt < 2; mt++)
#pragma unroll
        for (int nt = 0; nt < 8; nt++)
#pragma unroll
            for (int e = 0; e < 4; e++) d[mt][nt][e] = 0.0f;

#define FPREF(kc) do {                                                          \
        int buf_ = (kc) & 1;                                                    \
        const __half* as_ = ((kc) < 4) ? Ax + (size_t)row0 * HID + (kc) * FBK   \
                                       : Ah + (size_t)row0 * HID + ((kc)-4)*FBK;\
        _Pragma("unroll")                                                       \
        for (int i_ = 0; i_ < 4; i_++) {                                        \
            int idx_ = tid + i_ * 256;                                          \
            int r_ = idx_ >> 3, q_ = idx_ & 7;                                  \
            uint32_t ad_ = (uint32_t)__cvta_generic_to_shared(                  \
                               As + buf_ * FCHUNK + r_ * FPITCH + q_ * 8);      \
            cpa16(ad_, as_ + (size_t)r_ * HID + q_ * 8);                        \
            uint32_t bd_ = (uint32_t)__cvta_generic_to_shared(                  \
                               Bs + buf_ * FCHUNK + r_ * FPITCH + q_ * 8);      \
            cpa16(bd_, Wf + (size_t)(col0 + r_) * 512 + (kc) * FBK + q_ * 8);   \
        }                                                                       \
        asm volatile("cp.async.commit_group;");                                 \
    } while (0)

    FPREF(0);
    for (int kc = 0; kc < 8; kc++) {
        if (kc + 1 < 8) { FPREF(kc + 1); asm volatile("cp.async.wait_group 1;"); }
        else            { asm volatile("cp.async.wait_group 0;"); }
        __syncthreads();

        const __half* Ab = As + (kc & 1) * FCHUNK;
        const __half* Bb = Bs + (kc & 1) * FCHUNK;
        const int skipg = (kc < 4) ? 3 : 2;
#pragma unroll
        for (int ks = 0; ks < 4; ks++) {
            uint32_t a[2][4];
#pragma unroll
            for (int mt = 0; mt < 2; mt++) {
                const __half* ap = Ab + (wm * 32 + mt * 16 + gq) * FPITCH + ks * 16;
                a[mt][0] = *(const uint32_t*)(ap + 2 * tig);
                a[mt][1] = *(const uint32_t*)(ap + 8 * FPITCH + 2 * tig);
                a[mt][2] = *(const uint32_t*)(ap + 2 * tig + 8);
                a[mt][3] = *(const uint32_t*)(ap + 8 * FPITCH + 2 * tig + 8);
            }
#pragma unroll
            for (int nt = 0; nt < 8; nt++) {
                if ((nt & 3) == skipg) continue;
                const __half* bp = Bb + (wn * 64 + nt * 8 + gq) * FPITCH + ks * 16 + 2 * tig;
                uint32_t b[2];
                b[0] = *(const uint32_t*)bp;
                b[1] = *(const uint32_t*)(bp + 8);
                mma_f16(d[0][nt], a[0], b);
                mma_f16(d[1][nt], a[1], b);
            }
        }
        __syncthreads();
    }
#undef FPREF

    const float* gb = g_gb;
#pragma unroll
    for (int a2 = 0; a2 < 2; a2++) {
        const int J = (col0 >> 2) + wn * 16 + a2 * 8 + 2 * tig;
        const float bR0 = gb[J],       bR1 = gb[J + 1];
        const float bZ0 = gb[256 + J], bZ1 = gb[256 + J + 1];
        const float bI0 = gb[512 + J], bI1 = gb[512 + J + 1];
        const float bH0 = gb[768 + J], bH1 = gb[768 + J + 1];
#pragma unroll
        for (int mt = 0; mt < 2; mt++) {
            const int rowa = row0 + wm * 32 + mt * 16 + gq;
#pragma unroll
            for (int half = 0; half < 2; half++) {
                const int row = rowa + half * 8;
                const int e0 = half * 2, e1 = half * 2 + 1;
                float r0 = sigf(d[mt][4 * a2 + 0][e0] + bR0);
                float r1 = sigf(d[mt][4 * a2 + 0][e1] + bR1);
                float z0 = sigf(d[mt][4 * a2 + 1][e0] + bZ0);
                float z1 = sigf(d[mt][4 * a2 + 1][e1] + bZ1);
                float n0 = tanhfast(d[mt][4 * a2 + 2][e0] + bI0 + r0 * (d[mt][4 * a2 + 3][e0] + bH0));
                float n1 = tanhfast(d[mt][4 * a2 + 2][e1] + bI1 + r1 * (d[mt][4 * a2 + 3][e1] + bH1));
                float2 hp = *(const float2*)(hprev + (size_t)row * HID + J);
                float h0 = (1.0f - z0) * n0 + z0 * hp.x;
                float h1 = (1.0f - z1) * n1 + z1 * hp.y;
                *(float2*)(h32out + (size_t)row * HID + J) = make_float2(h0, h1);
                *(__half2*)(h16out + (size_t)row * HID + J) = __floats2half2_rn(h0, h1);
            }
        }
    }
}

// ================= cells 2/3: gates = h @ Wf2 + Sg[row/16] + bias (K=256) =================
__global__ __launch_bounds__(256, 2)
void fused_gru2(const __half* __restrict__ Ah, const float* __restrict__ hprev,
                const float* __restrict__ Sg, float* __restrict__ h32out,
                __half* __restrict__ h16out)
{
    extern __shared__ __half sm[];
    __half* As = sm;
    __half* Bs = sm + 2 * FCHUNK;
    const __half* Wf = g_wf2;

    const int tid = threadIdx.x;
    const int wid = tid >> 5, lid = tid & 31;
    const int wm = wid & 3, wn = wid >> 2;
    const int gq = lid >> 2, tig = lid & 3;
    const int row0 = blockIdx.y * 128;
    const int col0 = blockIdx.x * 128;

    float d[2][8][4];
#pragma unroll
    for (int mt = 0; mt < 2; mt++)
#pragma unroll
        for (int nt = 0; nt < 8; nt++)
#pragma unroll
            for (int e = 0; e < 4; e++) d[mt][nt][e] = 0.0f;

#define F2PREF(kc) do {                                                         \
        int buf_ = (kc) & 1;                                                    \
        _Pragma("unroll")                                                       \
        for (int i_ = 0; i_ < 4; i_++) {                                        \
            int idx_ = tid + i_ * 256;                                          \
            int r_ = idx_ >> 3, q_ = idx_ & 7;                                  \
            uint32_t ad_ = (uint32_t)__cvta_generic_to_shared(                  \
                               As + buf_ * FCHUNK + r_ * FPITCH + q_ * 8);      \
            cpa16(ad_, Ah + (size_t)(row0 + r_) * HID + (kc) * FBK + q_ * 8);   \
            uint32_t bd_ = (uint32_t)__cvta_generic_to_shared(                  \
                               Bs + buf_ * FCHUNK + r_ * FPITCH + q_ * 8);      \
            cpa16(bd_, Wf + (size_t)(col0 + r_) * 256 + (kc) * FBK + q_ * 8);   \
        }                                                                       \
        asm volatile("cp.async.commit_group;");                                 \
    } while (0)

    F2PREF(0);
    for (int kc = 0; kc < 4; kc++) {
        if (kc + 1 < 4) { F2PREF(kc + 1); asm volatile("cp.async.wait_group 1;"); }
        else            { asm volatile("cp.async.wait_group 0;"); }
        __syncthreads();

        const __half* Ab = As + (kc & 1) * FCHUNK;
        const __half* Bb = Bs + (kc & 1) * FCHUNK;
#pragma unroll
        for (int ks = 0; ks < 4; ks++) {
            uint32_t a[2][4];
#pragma unroll
            for (int mt = 0; mt < 2; mt++) {
                const __half* ap = Ab + (wm * 32 + mt * 16 + gq) * FPITCH + ks * 16;
                a[mt][0] = *(const uint32_t*)(ap + 2 * tig);
                a[mt][1] = *(const uint32_t*)(ap + 8 * FPITCH + 2 * tig);
                a[mt][2] = *(const uint32_t*)(ap + 2 * tig + 8);
                a[mt][3] = *(const uint32_t*)(ap + 8 * FPITCH + 2 * tig + 8);
            }
#pragma unroll
            for (int nt = 0; nt < 8; nt++) {
                const __half* bp = Bb + (wn * 64 + nt * 8 + gq) * FPITCH + ks * 16 + 2 * tig;
                uint32_t b[2];
                b[0] = *(const uint32_t*)bp;
                b[1] = *(const uint32_t*)(bp + 8);
                mma_f16(d[0][nt], a[0], b);
                mma_f16(d[1][nt], a[1], b);
            }
        }
        __syncthreads();
    }
#undef F2PREF

    const float* gb = g_gb;
#pragma unroll
    for (int a2 = 0; a2 < 2; a2++) {
        const int J = (col0 >> 2) + wn * 16 + a2 * 8 + 2 * tig;
        const float bR0 = gb[J],       bR1 = gb[J + 1];
        const float bZ0 = gb[256 + J], bZ1 = gb[256 + J + 1];
        const float bI0 = gb[512 + J], bI1 = gb[512 + J + 1];
        const float bH0 = gb[768 + J], bH1 = gb[768 + J + 1];
#pragma unroll
        for (int mt = 0; mt < 2; mt++) {
            const int rowa = row0 + wm * 32 + mt * 16 + gq;
#pragma unroll
            for (int half = 0; half < 2; half++) {
                const int row = rowa + half * 8;
                const int e0 = half * 2, e1 = half * 2 + 1;
                const float* sgr = Sg + (size_t)(row >> 4) * 768 + J;
                float2 sR = *(const float2*)(sgr);
                float2 sZ = *(const float2*)(sgr + 256);
                float2 sI = *(const float2*)(sgr + 512);
                float r0 = sigf(d[mt][4 * a2 + 0][e0] + sR.x + bR0);
                float r1 = sigf(d[mt][4 * a2 + 0][e1] + sR.y + bR1);
                float z0 = sigf(d[mt][4 * a2 + 1][e0] + sZ.x + bZ0);
                float z1 = sigf(d[mt][4 * a2 + 1][e1] + sZ.y + bZ1);
                float n0 = tanhfast(d[mt][4 * a2 + 2][e0] + sI.x + bI0 + r0 * (d[mt][4 * a2 + 3][e0] + bH0));
                float n1 = tanhfast(d[mt][4 * a2 + 2][e1] + sI.y + bI1 + r1 * (d[mt][4 * a2 + 3][e1] + bH1));
                float2 hp = *(const float2*)(hprev + (size_t)row * HID + J);
                float h0 = (1.0f - z0) * n0 + z0 * hp.x;
                float h1 = (1.0f - z1) * n1 + z1 * hp.y;
                *(float2*)(h32out + (size_t)row * HID + J) = make_float2(h0, h1);
                *(__half2*)(h16out + (size_t)row * HID + J) = __floats2half2_rn(h0, h1);
            }
        }
    }
}

// ================= generic fp16 GEMM (encoder / decoder / Sg) =================
__global__ __launch_bounds__(256, 2)
void hgemm(const __half* __restrict__ A, const __half* __restrict__ W,
           const float* __restrict__ bias, float* __restrict__ C32,
           __half* __restrict__ C16, int K, int N, int act)
{
    extern __shared__ __half sm[];
    __half* As = sm;
    __half* Bs = sm + 2 * FCHUNK;

    const int tid = threadIdx.x;
    const int wid = tid >> 5, lid = tid & 31;
    const int wm = wid & 3, wn = wid >> 2;
    const int gq = lid >> 2, tig = lid & 3;
    const int row0 = blockIdx.y * 128;
    const int col0 = blockIdx.x * 128;
    const int NC = K / FBK;

    float d[2][8][4];
#pragma unroll
    for (int mt = 0; mt < 2; mt++)
#pragma unroll
        for (int nt = 0; nt < 8; nt++)
#pragma unroll
            for (int e = 0; e < 4; e++) d[mt][nt][e] = 0.0f;

#define GPREF(kc) do {                                                          \
        int buf_ = (kc) & 1;                                                    \
        _Pragma("unroll")                                                       \
        for (int i_ = 0; i_ < 4; i_++) {                                        \
            int idx_ = tid + i_ * 256;                                          \
            int r_ = idx_ >> 3, q_ = idx_ & 7;                                  \
            uint32_t ad_ = (uint32_t)__cvta_generic_to_shared(                  \
                               As + buf_ * FCHUNK + r_ * FPITCH + q_ * 8);      \
            cpa16(ad_, A + (size_t)(row0 + r_) * K + (kc) * FBK + q_ * 8);      \
            uint32_t bd_ = (uint32_t)__cvta_generic_to_shared(                  \
                               Bs + buf_ * FCHUNK + r_ * FPITCH + q_ * 8);      \
            cpa16z(bd_, W + (size_t)(col0 + r_) * K + (kc) * FBK + q_ * 8,      \
                   col0 + r_ < N);                                              \
        }                                                                       \
        asm volatile("cp.async.commit_group;");                                 \
    } while (0)

    GPREF(0);
    for (int kc = 0; kc < NC; kc++) {
        if (kc + 1 < NC) { GPREF(kc + 1); asm volatile("cp.async.wait_group 1;"); }
        else             { asm volatile("cp.async.wait_group 0;"); }
        __syncthreads();

        const __half* Ab = As + (kc & 1) * FCHUNK;
        const __half* Bb = Bs + (kc & 1) * FCHUNK;
#pragma unroll
        for (int ks = 0; ks < 4; ks++) {
            uint32_t a[2][4];
#pragma unroll
            for (int mt = 0; mt < 2; mt++) {
                const __half* ap = Ab + (wm * 32 + mt * 16 + gq) * FPITCH + ks * 16;
                a[mt][0] = *(const uint32_t*)(ap + 2 * tig);
                a[mt][1] = *(const uint32_t*)(ap + 8 * FPITCH + 2 * tig);
                a[mt][2] = *(const uint32_t*)(ap + 2 * tig + 8);
                a[mt][3] = *(const uint32_t*)(ap + 8 * FPITCH + 2 * tig + 8);
            }
#pragma unroll
            for (int nt = 0; nt < 8; nt++) {
                const __half* bp = Bb + (wn * 64 + nt * 8 + gq) * FPITCH + ks * 16 + 2 * tig;
                uint32_t b[2];
                b[0] = *(const uint32_t*)bp;
                b[1] = *(const uint32_t*)(bp + 8);
                mma_f16(d[0][nt], a[0], b);
                mma_f16(d[1][nt], a[1], b);
            }
        }
        __syncthreads();
    }
#undef GPREF

#pragma unroll
    for (int nt = 0; nt < 8; nt++) {
        int col = col0 + wn * 64 + nt * 8 + 2 * tig;
        if (col < N) {
            float b0 = bias ? bias[col]     : 0.0f;
            float b1 = bias ? bias[col + 1] : 0.0f;
#pragma unroll
            for (int mt = 0; mt < 2; mt++) {
                int rowa = row0 + wm * 32 + mt * 16 + gq;
#pragma unroll
                for (int half = 0; half < 2; half++) {
                    int row = rowa + half * 8;
                    float v0 = d[mt][nt][half * 2]     + b0;
                    float v1 = d[mt][nt][half * 2 + 1] + b1;
                    if (act) { v0 = sigf(v0); v1 = sigf(v1); }
                    if (C32) *(float2*)(C32 + (size_t)row * N + col) = make_float2(v0, v1);
                    if (C16) *(__half2*)(C16 + (size_t)row * N + col) = __floats2half2_rn(v0, v1);
                }
            }
        }
    }
}

// ================= prep + elementwise kernels =================
__global__ void f2h_kernel(const float4* __restrict__ src, __half2* __restrict__ dst, int n4)
{
    int i = blockIdx.x * blockDim.x + threadIdx.x;
    if (i < n4) {
        float4 v = src[i];
        dst[2 * i]     = __floats2half2_rn(v.x, v.y);
        dst[2 * i + 1] = __floats2half2_rn(v.z, v.w);
    }
}

__global__ void f2h_scale_kernel(const float4* __restrict__ src, __half2* __restrict__ dst,
                                 int n4, float scale)
{
    int i = blockIdx.x * blockDim.x + threadIdx.x;
    if (i < n4) {
        float4 v = src[i];
        dst[2 * i]     = __floats2half2_rn(v.x * scale, v.y * scale);
        dst[2 * i + 1] = __floats2half2_rn(v.z * scale, v.w * scale);
    }
}

__global__ void build_wf_kernel(const float* __restrict__ w_ih, const float* __restrict__ w_hh)
{
    int idx = blockIdx.x * blockDim.x + threadIdx.x;   // 1024*512
    if (idx >= 1024 * 512) return;
    int c = idx >> 9, k = idx & 511;
    int g = (c >> 3) & 3;
    int j = ((c >> 5) << 3) + (c & 7);
    float v;
    if (g == 0)      v = (k < 256) ? w_ih[j * 256 + k]           : w_hh[j * 256 + k - 256];
    else if (g == 1) v = (k < 256) ? w_ih[(256 + j) * 256 + k]   : w_hh[(256 + j) * 256 + k - 256];
    else if (g == 2) v = (k < 256) ? w_ih[(512 + j) * 256 + k]   : 0.0f;
    else             v = (k < 256) ? 0.0f                        : w_hh[(512 + j) * 256 + k - 256];
    g_wf[c * 512 + k] = __float2half_rn(v);
}

// W' for cells 2/3: r: Whh_r - Wih_r/16 ; z: Whh_z - Wih_z/16 ; i_n: -Wih_n/16 ; h_n: Whh_n
__global__ void build_wf2_kernel(const float* __restrict__ w_ih, const float* __restrict__ w_hh)
{
    int idx = blockIdx.x * blockDim.x + threadIdx.x;   // 1024*256
    if (idx >= 1024 * 256) return;
    int c = idx >> 8, k = idx & 255;
    int g = (c >> 3) & 3;
    int j = ((c >> 5) << 3) + (c & 7);
    const float inv = 1.0f / (float)N_AGENTS;
    float v;
    if (g == 0)      v = w_hh[j * 256 + k]         - w_ih[j * 256 + k] * inv;
    else if (g == 1) v = w_hh[(256 + j) * 256 + k] - w_ih[(256 + j) * 256 + k] * inv;
    else if (g == 2) v = -w_ih[(512 + j) * 256 + k] * inv;
    else             v = w_hh[(512 + j) * 256 + k];
    g_wf2[c * 256 + k] = __float2half_rn(v);
}

__global__ void build_gb_kernel(const float* __restrict__ b_ih, const float* __restrict__ b_hh)
{
    int idx = threadIdx.x + blockIdx.x * blockDim.x;   // 1024
    if (idx >= 1024) return;
    int g = idx >> 8, j = idx & 255;
    float v;
    if (g == 0)      v = b_ih[j] + b_hh[j];
    else if (g == 1) v = b_ih[256 + j] + b_hh[256 + j];
    else if (g == 2) v = b_ih[512 + j];
    else             v = b_hh[512 + j];
    g_gb[idx] = v;
}

// per-group agent sum: S[b][:] = sum_a h[b*16+a][:]   (fp32 accum, fp16 out)
__global__ void sum_kernel(const __half2* __restrict__ h, __half2* __restrict__ S)
{
    int t = blockIdx.x * blockDim.x + threadIdx.x;     // NGROUP * 128
    int b = t >> 7, j = t & 127;
    const __half2* hb = h + (size_t)b * (N_AGENTS * 128) + j;
    float sx = 0.f, sy = 0.f;
#pragma unroll
    for (int a = 0; a < N_AGENTS; a++) {
        float2 v = __half22float2(hb[a * 128]);
        sx += v.x; sy += v.y;
    }
    S[(size_t)b * 128 + j] = __floats2half2_rn(sx, sy);
}

extern "C" void kernel_launch(void* const* d_in, const int* in_sizes, int n_in,
                              void* d_out, int out_size)
{
    const float* obs   = (const float*)d_in[0];
    const float* h0    = (const float*)d_in[1];
    const float* enc_w = (const float*)d_in[2];
    const float* enc_b = (const float*)d_in[3];
    const float* w_ih  = (const float*)d_in[4];
    const float* w_hh  = (const float*)d_in[5];
    const float* b_ih  = (const float*)d_in[6];
    const float* b_hh  = (const float*)d_in[7];
    const float* dec_w = (const float*)d_in[8];
    const float* dec_b = (const float*)d_in[9];
    float* out = (float*)d_out;

    __half *x16, *h16a, *h16b, *obs16, *h016, *encw, *decw, *ws16, *S16;
    float *h32a, *h32b, *Sg;
    cudaGetSymbolAddress((void**)&x16,   g_x16);
    cudaGetSymbolAddress((void**)&h16a,  g_h16a);
    cudaGetSymbolAddress((void**)&h16b,  g_h16b);
    cudaGetSymbolAddress((void**)&h32a,  g_h32a);
    cudaGetSymbolAddress((void**)&h32b,  g_h32b);
    cudaGetSymbolAddress((void**)&obs16, g_obs16);
    cudaGetSymbolAddress((void**)&h016,  g_h016);
    cudaGetSymbolAddress((void**)&encw,  g_encw);
    cudaGetSymbolAddress((void**)&decw,  g_decw);
    cudaGetSymbolAddress((void**)&ws16,  g_ws16);
    cudaGetSymbolAddress((void**)&S16,   g_S16);
    cudaGetSymbolAddress((void**)&Sg,    g_Sg);

    cudaFuncSetAttribute(fused_gru,  cudaFuncAttributeMaxDynamicSharedMemorySize, FSMEM_BYTES);
    cudaFuncSetAttribute(fused_gru2, cudaFuncAttributeMaxDynamicSharedMemorySize, FSMEM_BYTES);
    cudaFuncSetAttribute(hgemm,      cudaFuncAttributeMaxDynamicSharedMemorySize, FSMEM_BYTES);

    // ---- prep ----
    f2h_kernel<<<(ROWS * OBS_DIM / 4 + 255) / 256, 256>>>((const float4*)obs, (__half2*)obs16, ROWS * OBS_DIM / 4);
    f2h_kernel<<<(ROWS * HID / 4 + 255) / 256, 256>>>((const float4*)h0, (__half2*)h016, ROWS * HID / 4);
    f2h_kernel<<<(HID * OBS_DIM / 4 + 255) / 256, 256>>>((const float4*)enc_w, (__half2*)encw, HID * OBS_DIM / 4);
    f2h_kernel<<<(N_ACTIONS * HID / 4 + 255) / 256, 256>>>((const float4*)dec_w, (__half2*)decw, N_ACTIONS * HID / 4);
    f2h_scale_kernel<<<(768 * 256 / 4 + 255) / 256, 256>>>((const float4*)w_ih, (__half2*)ws16,
                                                           768 * 256 / 4, 1.0f / (float)N_AGENTS);
    build_wf_kernel<<<(1024 * 512) / 256, 256>>>(w_ih, w_hh);
    build_wf2_kernel<<<(1024 * 256) / 256, 256>>>(w_ih, w_hh);
    build_gb_kernel<<<4, 256>>>(b_ih, b_hh);

    dim3 t(256);
    const int sumBlocks = (NGROUP * 128) / 256;      // 4096

    // encoder
    hgemm<<<dim3(2, ROWS / 128), t, FSMEM_BYTES>>>(obs16, encw, enc_b, nullptr, x16, OBS_DIM, HID, 1);

    // cell 1
    fused_gru<<<dim3(8, ROWS / 128), t, FSMEM_BYTES>>>(x16, h016, h0, h32a, h16a);

    // comm 1 (S + Sg) + cell 2
    sum_kernel<<<sumBlocks, 256>>>((const __half2*)h16a, (__half2*)S16);
    hgemm<<<dim3(6, NGROUP / 128), t, FSMEM_BYTES>>>(S16, ws16, nullptr, Sg, nullptr, HID, 768, 0);
    fused_gru2<<<dim3(8, ROWS / 128), t, FSMEM_BYTES>>>(h16a, h32a, Sg, h32b, h16b);

    // comm 2 + cell 3 (h32 straight into d_out tail)
    sum_kernel<<<sumBlocks, 256>>>((const __half2*)h16b, (__half2*)S16);
    hgemm<<<dim3(6, NGROUP / 128), t, FSMEM_BYTES>>>(S16, ws16, nullptr, Sg, nullptr, HID, 768, 0);
    fused_gru2<<<dim3(8, ROWS / 128), t, FSMEM_BYTES>>>(h16b, h32b, Sg,
                                                        out + (size_t)ROWS * N_ACTIONS, h16a);

    // decoder
    hgemm<<<dim3(1, ROWS / 128), t, FSMEM_BYTES>>>(h16a, decw, dec_b, out, nullptr, HID, N_ACTIONS, 0);
}